// round 5
// baseline (speedup 1.0000x reference)
#include <cuda_runtime.h>
#include <math_constants.h>

// RoiMaxPooling: x (256,56,56,256) f32 NHWC -> adaptive 7x7 max pool (8x8 bins)
// with the reference's transpose/reshape index scramble:
//   out_linear_row = w*(7*B) + h*B + b
//
// R5: persistent single-wave launch (148 SMs x 3 CTAs = 444 blocks),
// grid-striding the quad index. At any instant the active set reads one
// contiguous ~113MB window sweeping the tensor front-to-back (DRAM row
// locality), no wave-transition gaps, tail imbalance <= 1 quad.
// Body identical to R4 (deep 8-wide tree, __ldcs/__stcs, 3 CTAs/SM).

#define B_   256
#define HH   56
#define WW   56
#define CC   256
#define GH   7
#define GW   7

#define NQUADS   (B_ * GH * GW / 4)   // 3136
#define NBLOCKS  (148 * 3)            // 444 — one full wave at 3 CTAs/SM

__device__ __forceinline__ float4 vmax4(float4 a, float4 b) {
    return make_float4(fmaxf(a.x, b.x), fmaxf(a.y, b.y),
                       fmaxf(a.z, b.z), fmaxf(a.w, b.w));
}

__global__ __launch_bounds__(256, 3)
void roi_maxpool_kernel(const float4* __restrict__ x, float4* __restrict__ out) {
    const int t    = threadIdx.x;
    const int sub  = t >> 6;     // bin-within-quad 0..3
    const int lane = t & 63;     // channel-group 0..63

    const int C4  = CC / 4;      // 64 float4 per pixel
    const int ROW = WW * C4;     // float4 per H-row (3584)

    for (int q = blockIdx.x; q < NQUADS; q += NBLOCKS) {
        const int bin = (q << 2) + sub;

        const int b  = bin / (GH * GW);
        const int hw = bin - b * (GH * GW);
        const int h  = hw / GW;
        const int w  = hw - h * GW;

        const int base = ((b * HH + h * 8) * WW + w * 8) * C4 + lane;

        float4 acc = make_float4(-CUDART_INF_F, -CUDART_INF_F,
                                 -CUDART_INF_F, -CUDART_INF_F);

        #pragma unroll
        for (int i = 0; i < 8; i++) {
            const float4* rp = x + base + i * ROW;
            float4 v0 = __ldcs(rp + 0 * C4);
            float4 v1 = __ldcs(rp + 1 * C4);
            float4 v2 = __ldcs(rp + 2 * C4);
            float4 v3 = __ldcs(rp + 3 * C4);
            float4 v4 = __ldcs(rp + 4 * C4);
            float4 v5 = __ldcs(rp + 5 * C4);
            float4 v6 = __ldcs(rp + 6 * C4);
            float4 v7 = __ldcs(rp + 7 * C4);
            float4 a01 = vmax4(v0, v1);
            float4 a23 = vmax4(v2, v3);
            float4 a45 = vmax4(v4, v5);
            float4 a67 = vmax4(v6, v7);
            float4 a03 = vmax4(a01, a23);
            float4 a47 = vmax4(a45, a67);
            acc = vmax4(acc, vmax4(a03, a47));
        }

        const int orow = (w * (GH * B_) + h * B_ + b);
        __stcs(out + orow * C4 + lane, acc);
    }
}

extern "C" void kernel_launch(void* const* d_in, const int* in_sizes, int n_in,
                              void* d_out, int out_size) {
    const float4* x = (const float4*)d_in[0];
    float4* out = (float4*)d_out;
    roi_maxpool_kernel<<<NBLOCKS, 256>>>(x, out);
}

// round 6
// speedup vs baseline: 1.0822x; 1.0822x over previous
#include <cuda_runtime.h>
#include <math_constants.h>

// RoiMaxPooling: x (256,56,56,256) f32 NHWC -> adaptive 7x7 max pool (8x8 bins)
// with the reference's transpose/reshape index scramble:
//   out_linear_row = w*(7*B) + h*B + b
//
// R6: combine the two best-measured features:
//   - R1 geometry: classic 3136-block launch, __launch_bounds__(256,2)
//     -> ptxas uses ~128 regs and front-batches ~24 LDG.128/thread
//     (highest measured DRAM%: 88.6%)
//   - R4 cache policy: __ldcs/__stcs evict-first on the read-once/write-once
//     streams (-0.4us measured on the R3 base)
// R5's persistent grid-stride REGRESSED (loop-carried store/branch broke
// cross-row load pipelining) -- reverted to classic launch.

#define B_   256
#define HH   56
#define WW   56
#define CC   256
#define GH   7
#define GW   7

__device__ __forceinline__ float4 vmax4(float4 a, float4 b) {
    return make_float4(fmaxf(a.x, b.x), fmaxf(a.y, b.y),
                       fmaxf(a.z, b.z), fmaxf(a.w, b.w));
}

__global__ __launch_bounds__(256, 2)
void roi_maxpool_kernel(const float4* __restrict__ x, float4* __restrict__ out) {
    // 4 bins per 256-thread block; 64 threads per bin; 4 channels (float4) per thread.
    const int t    = threadIdx.x;
    const int bin  = (blockIdx.x << 2) + (t >> 6);   // 0 .. 256*49-1
    const int lane = t & 63;                          // channel-group 0..63

    const int b  = bin / (GH * GW);
    const int hw = bin - b * (GH * GW);
    const int h  = hw / GW;
    const int w  = hw - h * GW;

    const int C4  = CC / 4;        // 64 float4 per pixel
    const int ROW = WW * C4;       // float4 per H-row (3584)

    // base pixel of this 8x8 window
    const int base = ((b * HH + h * 8) * WW + w * 8) * C4 + lane;

    float4 acc = make_float4(-CUDART_INF_F, -CUDART_INF_F,
                             -CUDART_INF_F, -CUDART_INF_F);

    #pragma unroll
    for (int i = 0; i < 8; i++) {
        const float4* rp = x + base + i * ROW;
        // 8 independent streaming LDG.128 per row, tree-reduced; at the
        // 2-CTA register budget ptxas software-pipelines ~3 rows deep.
        float4 v0 = __ldcs(rp + 0 * C4);
        float4 v1 = __ldcs(rp + 1 * C4);
        float4 v2 = __ldcs(rp + 2 * C4);
        float4 v3 = __ldcs(rp + 3 * C4);
        float4 v4 = __ldcs(rp + 4 * C4);
        float4 v5 = __ldcs(rp + 5 * C4);
        float4 v6 = __ldcs(rp + 6 * C4);
        float4 v7 = __ldcs(rp + 7 * C4);
        float4 a01 = vmax4(v0, v1);
        float4 a23 = vmax4(v2, v3);
        float4 a45 = vmax4(v4, v5);
        float4 a67 = vmax4(v6, v7);
        float4 a03 = vmax4(a01, a23);
        float4 a47 = vmax4(a45, a67);
        acc = vmax4(acc, vmax4(a03, a47));
    }

    // Scrambled destination: linear row = w*(GH*B) + h*B + b
    const int orow = (w * (GH * B_) + h * B_ + b);
    __stcs(out + orow * C4 + lane, acc);
}

extern "C" void kernel_launch(void* const* d_in, const int* in_sizes, int n_in,
                              void* d_out, int out_size) {
    const float4* x = (const float4*)d_in[0];
    float4* out = (float4*)d_out;
    const int n_bins = B_ * GH * GW;          // 12544
    const int blocks = n_bins / 4;            // 3136
    roi_maxpool_kernel<<<blocks, 256>>>(x, out);
}

// round 7
// speedup vs baseline: 1.0929x; 1.0099x over previous
#include <cuda_runtime.h>
#include <math_constants.h>

// RoiMaxPooling: x (256,56,56,256) f32 NHWC -> adaptive 7x7 max pool (8x8 bins)
// with the reference's transpose/reshape index scramble:
//   out_linear_row = w*(7*B) + h*B + b
//
// R7: TWO independent bins per thread. Previous kernels gave each thread a
// single dependency chain (loads -> tree -> acc join drains the pipe every
// row). Two chains interleave freely in the scheduler: when chain A hits its
// vmax join, chain B's loads issue -> per-thread effective MLP ~doubles at
// the same register budget. Geometry = R1/R6 (best measured DRAM%):
// 256 thr, 2 CTAs/SM, classic launch, __ldcs/__stcs streaming hints.

#define B_   256
#define HH   56
#define WW   56
#define CC   256
#define GH   7
#define GW   7

__device__ __forceinline__ float4 vmax4(float4 a, float4 b) {
    return make_float4(fmaxf(a.x, b.x), fmaxf(a.y, b.y),
                       fmaxf(a.z, b.z), fmaxf(a.w, b.w));
}

__global__ __launch_bounds__(256, 2)
void roi_maxpool_kernel(const float4* __restrict__ x, float4* __restrict__ out) {
    // Block covers 8 bins: 4 thread-groups of 64 threads, each group owns
    // 2 consecutive bins (two independent chains per thread).
    const int t    = threadIdx.x;
    const int grp  = t >> 6;                          // 0..3
    const int lane = t & 63;                          // channel-group 0..63
    const int bin0 = (blockIdx.x << 3) + (grp << 1);  // even bin
    const int bin1 = bin0 + 1;                        // odd bin

    const int C4  = CC / 4;        // 64 float4 per pixel
    const int ROW = WW * C4;       // float4 per H-row (3584)

    // bin0 coords
    const int b0  = bin0 / (GH * GW);
    const int hw0 = bin0 - b0 * (GH * GW);
    const int h0  = hw0 / GW;
    const int w0  = hw0 - h0 * GW;
    // bin1 coords
    const int b1  = bin1 / (GH * GW);
    const int hw1 = bin1 - b1 * (GH * GW);
    const int h1  = hw1 / GW;
    const int w1  = hw1 - h1 * GW;

    const int base0 = ((b0 * HH + h0 * 8) * WW + w0 * 8) * C4 + lane;
    const int base1 = ((b1 * HH + h1 * 8) * WW + w1 * 8) * C4 + lane;

    float4 accA = make_float4(-CUDART_INF_F, -CUDART_INF_F,
                              -CUDART_INF_F, -CUDART_INF_F);
    float4 accB = accA;

    #pragma unroll
    for (int i = 0; i < 8; i++) {
        const float4* ra = x + base0 + i * ROW;
        const float4* rb = x + base1 + i * ROW;
        // chain A: 8 streaming LDG.128
        float4 a0 = __ldcs(ra + 0 * C4);
        float4 a1 = __ldcs(ra + 1 * C4);
        float4 a2 = __ldcs(ra + 2 * C4);
        float4 a3 = __ldcs(ra + 3 * C4);
        float4 a4 = __ldcs(ra + 4 * C4);
        float4 a5 = __ldcs(ra + 5 * C4);
        float4 a6 = __ldcs(ra + 6 * C4);
        float4 a7 = __ldcs(ra + 7 * C4);
        // chain B: 8 streaming LDG.128 (independent of chain A)
        float4 c0 = __ldcs(rb + 0 * C4);
        float4 c1 = __ldcs(rb + 1 * C4);
        float4 c2 = __ldcs(rb + 2 * C4);
        float4 c3 = __ldcs(rb + 3 * C4);
        float4 c4 = __ldcs(rb + 4 * C4);
        float4 c5 = __ldcs(rb + 5 * C4);
        float4 c6 = __ldcs(rb + 6 * C4);
        float4 c7 = __ldcs(rb + 7 * C4);

        float4 ta = vmax4(vmax4(vmax4(a0, a1), vmax4(a2, a3)),
                          vmax4(vmax4(a4, a5), vmax4(a6, a7)));
        float4 tb = vmax4(vmax4(vmax4(c0, c1), vmax4(c2, c3)),
                          vmax4(vmax4(c4, c5), vmax4(c6, c7)));
        accA = vmax4(accA, ta);
        accB = vmax4(accB, tb);
    }

    // Scrambled destinations: linear row = w*(GH*B) + h*B + b
    const int orow0 = (w0 * (GH * B_) + h0 * B_ + b0);
    const int orow1 = (w1 * (GH * B_) + h1 * B_ + b1);
    __stcs(out + orow0 * C4 + lane, accA);
    __stcs(out + orow1 * C4 + lane, accB);
}

extern "C" void kernel_launch(void* const* d_in, const int* in_sizes, int n_in,
                              void* d_out, int out_size) {
    const float4* x = (const float4*)d_in[0];
    float4* out = (float4*)d_out;
    const int n_bins = B_ * GH * GW;          // 12544
    const int blocks = n_bins / 8;            // 1568
    roi_maxpool_kernel<<<blocks, 256>>>(x, out);
}